// round 1
// baseline (speedup 1.0000x reference)
#include <cuda_runtime.h>

// Problem constants (fixed by the reference setup_inputs)
#define B   16
#define C   85
#define H   128
#define W   128
#define HW  (H * W)        // 16384
#define NT  64             // targets per image
#define NC  80             // num classes = C - 5
#define NCH 81             // channels 4..84 (obj + cls)

// Global accumulators (graph-capturable scratch; re-zeroed every launch)
// [0] = sum softplus(obj channel)
// [1] = sum softplus(cls channels)
// [2] = sum (1 - iou) box loss
// [3] = obj correction: sum of x_obj at unique assigned cells
// [4] = cls correction: sum of x_cls at unique (cell, cls) pairs
__device__ double g_acc[5];

__global__ void init_kernel() {
    if (threadIdx.x < 5) g_acc[threadIdx.x] = 0.0;
}

__device__ __forceinline__ float softplus_f(float x) {
    // matches jax.nn.softplus = logaddexp(x, 0) = max(x,0) + log1p(exp(-|x|))
    return fmaxf(x, 0.0f) + log1pf(expf(-fabsf(x)));
}

// One block per (batch, channel) row: bid in [0, B*81). Each row is 16384
// contiguous floats = 4096 float4. 256 threads x 16 vec loads each.
__global__ __launch_bounds__(256) void reduce_kernel(const float* __restrict__ preds) {
    const int bid = blockIdx.x;
    const int b   = bid / NCH;
    const int c   = 4 + (bid - b * NCH);   // channel 4..84

    const float4* __restrict__ p =
        reinterpret_cast<const float4*>(preds + ((size_t)b * C + c) * HW);

    float acc = 0.0f;
#pragma unroll
    for (int i = 0; i < 16; i++) {
        float4 v = p[threadIdx.x + i * 256];
        acc += softplus_f(v.x) + softplus_f(v.y) + softplus_f(v.z) + softplus_f(v.w);
    }

    __shared__ float sh[256];
    sh[threadIdx.x] = acc;
    __syncthreads();
#pragma unroll
    for (int s = 128; s > 0; s >>= 1) {
        if (threadIdx.x < s) sh[threadIdx.x] += sh[threadIdx.x + s];
        __syncthreads();
    }
    if (threadIdx.x == 0) {
        atomicAdd(&g_acc[(c == 4) ? 0 : 1], (double)sh[0]);
    }
}

// One block per batch image, NT threads (one per target).
__global__ __launch_bounds__(NT) void targets_kernel(const float* __restrict__ preds,
                                                     const float* __restrict__ tg) {
    const int b = blockIdx.x;
    const int n = threadIdx.x;

    __shared__ int   s_idx[NT];
    __shared__ int   s_cls[NT];
    __shared__ float s_box[NT], s_obj[NT], s_clsv[NT];

    const float* t = tg + ((size_t)b * NT + n) * 5;
    const int   cls = (int)t[0];
    const float cx = t[1], cy = t[2], w = t[3], h = t[4];

    const int gi = (int)(cx * (float)W);
    const int gj = (int)(cy * (float)H);
    const int idx = gj * W + gi;

    s_idx[n] = idx;
    s_cls[n] = cls;
    __syncthreads();

    // set-scatter semantics: only the first target claiming a cell / (cell,cls)
    // contributes to the BCE correction term.
    bool first_obj = true, first_cls = true;
    for (int m = 0; m < n; m++) {
        if (s_idx[m] == idx) {
            first_obj = false;
            if (s_cls[m] == cls) first_cls = false;
        }
    }

    const float* pb = preds + (size_t)b * C * HW + idx;
    const float px = pb[0 * HW];
    const float py = pb[1 * HW];
    const float pw = pb[2 * HW];
    const float ph = pb[3 * HW];
    const float xo = pb[4 * HW];
    const float xc = pb[(size_t)(5 + cls) * HW];

    // paired IoU, same formulation as the reference
    const float p1 = px - pw * 0.5f, p2 = py - ph * 0.5f;
    const float p3 = px + pw * 0.5f, p4 = py + ph * 0.5f;
    const float g1 = (cx - w * 0.5f) * (float)W, g2 = (cy - h * 0.5f) * (float)H;
    const float g3 = (cx + w * 0.5f) * (float)W, g4 = (cy + h * 0.5f) * (float)H;

    const float ix1 = fmaxf(p1, g1), iy1 = fmaxf(p2, g2);
    const float ix2 = fminf(p3, g3), iy2 = fminf(p4, g4);
    const float inter = fmaxf(ix2 - ix1, 0.0f) * fmaxf(iy2 - iy1, 0.0f);
    const float a1 = (p3 - p1) * (p4 - p2);
    const float a2 = (g3 - g1) * (g4 - g2);
    const float iou = inter / (a1 + a2 - inter + 1e-7f);

    s_box[n]  = 1.0f - iou;
    s_obj[n]  = first_obj ? xo : 0.0f;
    s_clsv[n] = first_cls ? xc : 0.0f;
    __syncthreads();

    // block reduce (NT = 64)
#pragma unroll
    for (int s = NT / 2; s > 0; s >>= 1) {
        if (n < s) {
            s_box[n]  += s_box[n + s];
            s_obj[n]  += s_obj[n + s];
            s_clsv[n] += s_clsv[n + s];
        }
        __syncthreads();
    }
    if (n == 0) {
        atomicAdd(&g_acc[2], (double)s_box[0]);
        atomicAdd(&g_acc[3], (double)s_obj[0]);
        atomicAdd(&g_acc[4], (double)s_clsv[0]);
    }
}

__global__ void finalize_kernel(float* __restrict__ out) {
    const double obj_loss = (g_acc[0] - g_acc[3]) / (double)HW;
    const double cls_loss = (g_acc[1] - g_acc[4]) / ((double)HW * (double)NC);
    const double box_loss = g_acc[2];
    out[0] = (float)(0.05 * box_loss + 1.0 * obj_loss + 0.5 * cls_loss);
}

extern "C" void kernel_launch(void* const* d_in, const int* in_sizes, int n_in,
                              void* d_out, int out_size) {
    const float* preds   = (const float*)d_in[0];
    const float* targets = (const float*)d_in[1];
    float* out = (float*)d_out;

    init_kernel<<<1, 32>>>();
    reduce_kernel<<<B * NCH, 256>>>(preds);
    targets_kernel<<<B, NT>>>(preds, targets);
    finalize_kernel<<<1, 1>>>(out);
}

// round 2
// speedup vs baseline: 1.1537x; 1.1537x over previous
#include <cuda_runtime.h>

// Problem constants (fixed by the reference setup_inputs)
#define B   16
#define C   85
#define H   128
#define W   128
#define HW  (H * W)        // 16384
#define NT  64             // targets per image
#define NC  80             // num classes = C - 5
#define NCH 81             // channels 4..84 (obj + cls)

#define GRID_REDUCE (B * NCH)          // 1296 reduce blocks
#define GRID_TOTAL  (GRID_REDUCE + B)  // + 16 target blocks = 1312

// Global accumulators + completion counter. Zero at module load; the last
// block of every launch resets them, so each launch (and each graph replay)
// starts from a clean state.
// [0] = sum softplus(obj channel)
// [1] = sum softplus(cls channels)
// [2] = sum (1 - iou) box loss
// [3] = obj correction: sum of x_obj at unique assigned cells
// [4] = cls correction: sum of x_cls at unique (cell, cls) pairs
__device__ double        g_acc[5];
__device__ unsigned int  g_done;

__device__ __forceinline__ float softplus_f(float x) {
    // matches jax.nn.softplus = max(x,0) + log1p(exp(-|x|))
    return fmaxf(x, 0.0f) + log1pf(expf(-fabsf(x)));
}

__global__ __launch_bounds__(256) void fused_kernel(const float* __restrict__ preds,
                                                    const float* __restrict__ tg,
                                                    float* __restrict__ out) {
    const int bid = blockIdx.x;
    const int tid = threadIdx.x;

    __shared__ float sh[256];
    __shared__ float sh2[2 * NT];
    __shared__ int   s_key[NT];     // packed (idx<<7 | cls) per target

    if (bid < GRID_REDUCE) {
        // ---------- bulk softplus reduction over channels 4..84 ----------
        const int b = bid / NCH;
        const int c = 4 + (bid - b * NCH);

        const float4* __restrict__ p =
            reinterpret_cast<const float4*>(preds + ((size_t)b * C + c) * HW);

        float acc = 0.0f;
#pragma unroll
        for (int i = 0; i < 16; i++) {
            float4 v = p[tid + i * 256];
            acc += softplus_f(v.x) + softplus_f(v.y) + softplus_f(v.z) + softplus_f(v.w);
        }

        sh[tid] = acc;
        __syncthreads();
#pragma unroll
        for (int s = 128; s > 32; s >>= 1) {
            if (tid < s) sh[tid] += sh[tid + s];
            __syncthreads();
        }
        if (tid < 32) {
            float v = sh[tid] + sh[tid + 32];
#pragma unroll
            for (int o = 16; o > 0; o >>= 1)
                v += __shfl_down_sync(0xffffffffu, v, o);
            if (tid == 0)
                atomicAdd(&g_acc[(c == 4) ? 0 : 1], (double)v);
        }
    } else {
        // ---------- per-image target processing (16 blocks) ----------
        const int b = bid - GRID_REDUCE;
        const int n = tid;

        float box_v = 0.0f, obj_v = 0.0f, cls_v = 0.0f;

        if (n < NT) {
            const float* t = tg + ((size_t)b * NT + n) * 5;
            const int   cls = (int)t[0];
            const float cx = t[1], cy = t[2], w = t[3], h = t[4];

            const int gi  = (int)(cx * (float)W);
            const int gj  = (int)(cy * (float)H);
            const int idx = gj * W + gi;

            s_key[n] = (idx << 7) | cls;
        }
        __syncthreads();

        if (n < NT) {
            const float* t = tg + ((size_t)b * NT + n) * 5;
            const int   cls = (int)t[0];
            const float cx = t[1], cy = t[2], w = t[3], h = t[4];
            const int   idx = s_key[n] >> 7;

            // set-scatter semantics: only the first target claiming a cell /
            // (cell,cls) contributes to the BCE correction term.
            bool first_obj = true, first_cls = true;
            for (int m = 0; m < n; m++) {
                if ((s_key[m] >> 7) == idx) {
                    first_obj = false;
                    if (s_key[m] == s_key[n]) first_cls = false;
                }
            }

            const float* pb = preds + (size_t)b * C * HW + idx;
            const float px = pb[0 * HW];
            const float py = pb[1 * HW];
            const float pw = pb[2 * HW];
            const float ph = pb[3 * HW];
            const float xo = pb[4 * HW];
            const float xc = pb[(size_t)(5 + cls) * HW];

            const float p1 = px - pw * 0.5f, p2 = py - ph * 0.5f;
            const float p3 = px + pw * 0.5f, p4 = py + ph * 0.5f;
            const float g1 = (cx - w * 0.5f) * (float)W, g2 = (cy - h * 0.5f) * (float)H;
            const float g3 = (cx + w * 0.5f) * (float)W, g4 = (cy + h * 0.5f) * (float)H;

            const float ix1 = fmaxf(p1, g1), iy1 = fmaxf(p2, g2);
            const float ix2 = fminf(p3, g3), iy2 = fminf(p4, g4);
            const float inter = fmaxf(ix2 - ix1, 0.0f) * fmaxf(iy2 - iy1, 0.0f);
            const float a1 = (p3 - p1) * (p4 - p2);
            const float a2 = (g3 - g1) * (g4 - g2);
            const float iou = inter / (a1 + a2 - inter + 1e-7f);

            box_v = 1.0f - iou;
            obj_v = first_obj ? xo : 0.0f;
            cls_v = first_cls ? xc : 0.0f;
        }

        // warp-level reduce within the two active warps (NT=64)
#pragma unroll
        for (int o = 16; o > 0; o >>= 1) {
            box_v += __shfl_down_sync(0xffffffffu, box_v, o);
            obj_v += __shfl_down_sync(0xffffffffu, obj_v, o);
            cls_v += __shfl_down_sync(0xffffffffu, cls_v, o);
        }
        if (n < NT && (n & 31) == 0) {
            sh2[(n >> 5) * 3 + 0] = box_v;
            sh2[(n >> 5) * 3 + 1] = obj_v;
            sh2[(n >> 5) * 3 + 2] = cls_v;
        }
        __syncthreads();
        if (tid == 0) {
            atomicAdd(&g_acc[2], (double)(sh2[0] + sh2[3]));
            atomicAdd(&g_acc[3], (double)(sh2[1] + sh2[4]));
            atomicAdd(&g_acc[4], (double)(sh2[2] + sh2[5]));
        }
    }

    // ---------- last-block-done finalize ----------
    __syncthreads();
    if (tid == 0) {
        __threadfence();
        unsigned int ticket = atomicAdd(&g_done, 1u);
        if (ticket == GRID_TOTAL - 1) {
            // all other blocks' atomics are visible (fence + atomic ordering)
            const double obj_loss = (g_acc[0] - g_acc[3]) / (double)HW;
            const double cls_loss = (g_acc[1] - g_acc[4]) / ((double)HW * (double)NC);
            const double box_loss = g_acc[2];
            out[0] = (float)(0.05 * box_loss + 1.0 * obj_loss + 0.5 * cls_loss);
            // reset state for the next launch / graph replay
            g_acc[0] = 0.0; g_acc[1] = 0.0; g_acc[2] = 0.0;
            g_acc[3] = 0.0; g_acc[4] = 0.0;
            __threadfence();
            g_done = 0u;
        }
    }
}

extern "C" void kernel_launch(void* const* d_in, const int* in_sizes, int n_in,
                              void* d_out, int out_size) {
    const float* preds   = (const float*)d_in[0];
    const float* targets = (const float*)d_in[1];
    float* out = (float*)d_out;

    fused_kernel<<<GRID_TOTAL, 256>>>(preds, targets, out);
}

// round 3
// speedup vs baseline: 2.0728x; 1.7966x over previous
#include <cuda_runtime.h>

// Problem constants (fixed by the reference setup_inputs)
#define B   16
#define C   85
#define H   128
#define W   128
#define HW  (H * W)        // 16384
#define NT  64             // targets per image
#define NC  80             // num classes = C - 5
#define NCH 81             // channels 4..84 (obj + cls)

#define GRID_REDUCE (B * NCH)          // 1296 reduce blocks
#define GRID_TOTAL  (GRID_REDUCE + B)  // + 16 target blocks = 1312

// Global accumulators + completion counter. Zero at module load; the last
// block of every launch resets them, so each launch / graph replay starts clean.
// [0] = sum softplus(obj channel)
// [1] = sum softplus(cls channels)
// [2] = sum (1 - iou) box loss
// [3] = obj correction: sum of x_obj at unique assigned cells
// [4] = cls correction: sum of x_cls at unique (cell, cls) pairs
__device__ double        g_acc[5];
__device__ unsigned int  g_done;

// Fast softplus: max(x,0) + log(1 + exp(-|x|)) using hardware MUFU intrinsics.
// 2 MUFU + ~5 fma/alu ops instead of the ~20+ instr library chains.
__device__ __forceinline__ float softplus_f(float x) {
    return fmaxf(x, 0.0f) + __logf(1.0f + __expf(-fabsf(x)));
}

__global__ __launch_bounds__(256) void fused_kernel(const float* __restrict__ preds,
                                                    const float* __restrict__ tg,
                                                    float* __restrict__ out) {
    const int bid = blockIdx.x;
    const int tid = threadIdx.x;

    __shared__ float sh[256];
    __shared__ float sh2[8];
    __shared__ int   s_key[NT];     // packed (idx<<7 | cls) per target

    if (bid < GRID_REDUCE) {
        // ---------- bulk softplus reduction over channels 4..84 ----------
        const int b = bid / NCH;
        const int c = 4 + (bid - b * NCH);

        const float4* __restrict__ p =
            reinterpret_cast<const float4*>(preds + ((size_t)b * C + c) * HW);

        float acc = 0.0f;
#pragma unroll
        for (int i = 0; i < 16; i++) {
            float4 v = p[tid + i * 256];
            acc += softplus_f(v.x) + softplus_f(v.y) + softplus_f(v.z) + softplus_f(v.w);
        }

        sh[tid] = acc;
        __syncthreads();
#pragma unroll
        for (int s = 128; s > 32; s >>= 1) {
            if (tid < s) sh[tid] += sh[tid + s];
            __syncthreads();
        }
        if (tid < 32) {
            float v = sh[tid] + sh[tid + 32];
#pragma unroll
            for (int o = 16; o > 0; o >>= 1)
                v += __shfl_down_sync(0xffffffffu, v, o);
            if (tid == 0)
                atomicAdd(&g_acc[(c == 4) ? 0 : 1], (double)v);
        }
    } else {
        // ---------- per-image target processing (16 blocks) ----------
        const int b = bid - GRID_REDUCE;
        const int n = tid;

        float box_v = 0.0f, obj_v = 0.0f, cls_v = 0.0f;

        if (n < NT) {
            const float* t = tg + ((size_t)b * NT + n) * 5;
            const int   cls = (int)t[0];
            const float cx = t[1], cy = t[2];

            const int gi  = (int)(cx * (float)W);
            const int gj  = (int)(cy * (float)H);
            const int idx = gj * W + gi;

            s_key[n] = (idx << 7) | cls;
        }
        __syncthreads();

        if (n < NT) {
            const float* t = tg + ((size_t)b * NT + n) * 5;
            const int   cls = (int)t[0];
            const float cx = t[1], cy = t[2], w = t[3], h = t[4];
            const int   idx = s_key[n] >> 7;

            // set-scatter semantics: only the first target claiming a cell /
            // (cell,cls) contributes to the BCE correction term.
            bool first_obj = true, first_cls = true;
            for (int m = 0; m < n; m++) {
                if ((s_key[m] >> 7) == idx) {
                    first_obj = false;
                    if (s_key[m] == s_key[n]) first_cls = false;
                }
            }

            const float* pb = preds + (size_t)b * C * HW + idx;
            const float px = pb[0 * HW];
            const float py = pb[1 * HW];
            const float pw = pb[2 * HW];
            const float ph = pb[3 * HW];
            const float xo = pb[4 * HW];
            const float xc = pb[(size_t)(5 + cls) * HW];

            const float p1 = px - pw * 0.5f, p2 = py - ph * 0.5f;
            const float p3 = px + pw * 0.5f, p4 = py + ph * 0.5f;
            const float g1 = (cx - w * 0.5f) * (float)W, g2 = (cy - h * 0.5f) * (float)H;
            const float g3 = (cx + w * 0.5f) * (float)W, g4 = (cy + h * 0.5f) * (float)H;

            const float ix1 = fmaxf(p1, g1), iy1 = fmaxf(p2, g2);
            const float ix2 = fminf(p3, g3), iy2 = fminf(p4, g4);
            const float inter = fmaxf(ix2 - ix1, 0.0f) * fmaxf(iy2 - iy1, 0.0f);
            const float a1 = (p3 - p1) * (p4 - p2);
            const float a2 = (g3 - g1) * (g4 - g2);
            const float iou = inter / (a1 + a2 - inter + 1e-7f);

            box_v = 1.0f - iou;
            obj_v = first_obj ? xo : 0.0f;
            cls_v = first_cls ? xc : 0.0f;
        }

        // warp-level reduce within the two active warps (NT=64)
#pragma unroll
        for (int o = 16; o > 0; o >>= 1) {
            box_v += __shfl_down_sync(0xffffffffu, box_v, o);
            obj_v += __shfl_down_sync(0xffffffffu, obj_v, o);
            cls_v += __shfl_down_sync(0xffffffffu, cls_v, o);
        }
        if (n < NT && (n & 31) == 0) {
            sh2[(n >> 5) * 3 + 0] = box_v;
            sh2[(n >> 5) * 3 + 1] = obj_v;
            sh2[(n >> 5) * 3 + 2] = cls_v;
        }
        __syncthreads();
        if (tid == 0) {
            atomicAdd(&g_acc[2], (double)(sh2[0] + sh2[3]));
            atomicAdd(&g_acc[3], (double)(sh2[1] + sh2[4]));
            atomicAdd(&g_acc[4], (double)(sh2[2] + sh2[5]));
        }
    }

    // ---------- last-block-done finalize ----------
    __syncthreads();
    if (tid == 0) {
        __threadfence();
        unsigned int ticket = atomicAdd(&g_done, 1u);
        if (ticket == GRID_TOTAL - 1) {
            const double obj_loss = (g_acc[0] - g_acc[3]) / (double)HW;
            const double cls_loss = (g_acc[1] - g_acc[4]) / ((double)HW * (double)NC);
            const double box_loss = g_acc[2];
            out[0] = (float)(0.05 * box_loss + 1.0 * obj_loss + 0.5 * cls_loss);
            // reset state for the next launch / graph replay
            g_acc[0] = 0.0; g_acc[1] = 0.0; g_acc[2] = 0.0;
            g_acc[3] = 0.0; g_acc[4] = 0.0;
            __threadfence();
            g_done = 0u;
        }
    }
}

extern "C" void kernel_launch(void* const* d_in, const int* in_sizes, int n_in,
                              void* d_out, int out_size) {
    const float* preds   = (const float*)d_in[0];
    const float* targets = (const float*)d_in[1];
    float* out = (float*)d_out;

    fused_kernel<<<GRID_TOTAL, 256>>>(preds, targets, out);
}